// round 1
// baseline (speedup 1.0000x reference)
#include <cuda_runtime.h>
#include <math.h>

#define B_DIM 16
#define C_DIM 512
#define S_DIM 1024
#define NG    32
#define NH    8
#define HD    64

// Scratch (allocation-free: __device__ globals)
__device__ float g_h   [B_DIM * C_DIM * S_DIM];                 // 32 MB
__device__ float g_qkv [B_DIM * 3 * C_DIM * S_DIM];             // 96 MB
__device__ float g_attn[(size_t)B_DIM * NH * S_DIM * S_DIM];    // 512 MB
__device__ float g_o   [B_DIM * C_DIM * S_DIM];                 // 32 MB

// ---------------------------------------------------------------------------
// GroupNorm: one block per (batch, group). 16 channels x 1024 spatial.
// ---------------------------------------------------------------------------
__global__ void groupnorm_kernel(const float* __restrict__ x,
                                 const float* __restrict__ gamma,
                                 const float* __restrict__ beta,
                                 float* __restrict__ h) {
    const int bg = blockIdx.x;
    const int b = bg / NG, g = bg % NG;
    const int CPG = C_DIM / NG;                 // 16
    const int NEL = CPG * S_DIM;                // 16384
    const long base = ((long)b * C_DIM + (long)g * CPG) * S_DIM;
    const float* xp = x + base;
    float* hp = h + base;

    float sum = 0.f, sq = 0.f;
    for (int i = threadIdx.x; i < NEL; i += 256) {
        float v = xp[i];
        sum += v;
        sq  += v * v;
    }
    __shared__ float ssum[256], ssq[256];
    ssum[threadIdx.x] = sum;
    ssq[threadIdx.x]  = sq;
    __syncthreads();
    for (int s = 128; s > 0; s >>= 1) {
        if (threadIdx.x < s) {
            ssum[threadIdx.x] += ssum[threadIdx.x + s];
            ssq[threadIdx.x]  += ssq[threadIdx.x + s];
        }
        __syncthreads();
    }
    const float mean = ssum[0] * (1.f / NEL);
    const float var  = ssq[0] * (1.f / NEL) - mean * mean;
    const float inv  = rsqrtf(var + 1e-5f);

    for (int i = threadIdx.x; i < NEL; i += 256) {
        int c = g * CPG + (i >> 10);            // i / S_DIM
        hp[i] = (xp[i] - mean) * inv * gamma[c] + beta[c];
    }
}

// ---------------------------------------------------------------------------
// Softmax over rows of length 1024. One block (256 thr) per row.
// ---------------------------------------------------------------------------
__global__ void softmax_kernel(float* __restrict__ attn) {
    float* row = attn + (size_t)blockIdx.x * S_DIM;
    const int tid = threadIdx.x;

    float v[4];
#pragma unroll
    for (int i = 0; i < 4; i++) v[i] = row[tid + i * 256];

    float m = fmaxf(fmaxf(v[0], v[1]), fmaxf(v[2], v[3]));
    __shared__ float sred[256];
    sred[tid] = m;
    __syncthreads();
    for (int s = 128; s > 0; s >>= 1) {
        if (tid < s) sred[tid] = fmaxf(sred[tid], sred[tid + s]);
        __syncthreads();
    }
    const float rmax = sred[0];
    __syncthreads();

    float sum = 0.f;
#pragma unroll
    for (int i = 0; i < 4; i++) {
        v[i] = __expf(v[i] - rmax);
        sum += v[i];
    }
    sred[tid] = sum;
    __syncthreads();
    for (int s = 128; s > 0; s >>= 1) {
        if (tid < s) sred[tid] += sred[tid + s];
        __syncthreads();
    }
    const float rinv = 1.f / sred[0];
#pragma unroll
    for (int i = 0; i < 4; i++) row[tid + i * 256] = v[i] * rinv;
}

// ---------------------------------------------------------------------------
// Generic batched register-tiled SGEMM.
//   C[m,n] = alpha * sum_k a(m,k) * b(k,n)  (+ bias[m]) (+ resid[m,n])
//   A_KM:  A stored [K,M] (k rows, m contiguous) else [M,K]
//   B_KN:  B stored [K,N] (k rows, n contiguous) else [N,K]
// Batch z decomposed as (zo, zi) with zi in [0, nInner).
// Dims must divide tile sizes exactly (guaranteed by the shapes here).
// ---------------------------------------------------------------------------
template <int BM, int BN, int BK, bool A_KM, bool B_KN>
__global__ void sgemm_kernel(const float* __restrict__ A,
                             const float* __restrict__ B,
                             float* __restrict__ C,
                             const float* __restrict__ bias,
                             const float* __restrict__ resid,
                             int M, int N, int K,
                             int lda, int ldb, int ldc,
                             int nInner,
                             long sAo, long sAi,
                             long sBo, long sBi,
                             long sCo, long sCi,
                             long sR,
                             float alpha) {
    constexpr int TM = 8, TN = 8;
    constexpr int NT = (BM / TM) * (BN / TN);
    const int tid = threadIdx.x;
    const int tx = tid % (BN / TN);
    const int ty = tid / (BN / TN);

    const int z  = blockIdx.z;
    const int zo = z / nInner, zi = z % nInner;
    A += zo * sAo + zi * sAi;
    B += zo * sBo + zi * sBi;
    C += zo * sCo + zi * sCi;
    if (resid) resid += zo * sR;

    const int m0 = blockIdx.y * BM;
    const int n0 = blockIdx.x * BN;

    __shared__ __align__(16) float As[BK][BM + 4];
    __shared__ __align__(16) float Bs[BK][BN + 4];

    float acc[TM][TN];
#pragma unroll
    for (int i = 0; i < TM; i++)
#pragma unroll
        for (int j = 0; j < TN; j++) acc[i][j] = 0.f;

    for (int k0 = 0; k0 < K; k0 += BK) {
        // --- load A tile ---
        if (A_KM) {
            for (int idx = tid; idx < BK * BM; idx += NT) {
                int k = idx / BM, m = idx % BM;
                As[k][m] = A[(long)(k0 + k) * lda + (m0 + m)];
            }
        } else {
            for (int idx = tid; idx < BK * BM; idx += NT) {
                int m = idx / BK, k = idx % BK;
                As[k][m] = A[(long)(m0 + m) * lda + (k0 + k)];
            }
        }
        // --- load B tile ---
        if (B_KN) {
            for (int idx = tid; idx < BK * BN; idx += NT) {
                int k = idx / BN, n = idx % BN;
                Bs[k][n] = B[(long)(k0 + k) * ldb + (n0 + n)];
            }
        } else {
            for (int idx = tid; idx < BK * BN; idx += NT) {
                int n = idx / BK, k = idx % BK;
                Bs[k][n] = B[(long)(n0 + n) * ldb + (k0 + k)];
            }
        }
        __syncthreads();

#pragma unroll
        for (int k = 0; k < BK; k++) {
            float4 a0 = *(const float4*)&As[k][ty * 4];
            float4 a1 = *(const float4*)&As[k][BM / 2 + ty * 4];
            float4 b0 = *(const float4*)&Bs[k][tx * 4];
            float4 b1 = *(const float4*)&Bs[k][BN / 2 + tx * 4];
            float a[TM] = {a0.x, a0.y, a0.z, a0.w, a1.x, a1.y, a1.z, a1.w};
            float b[TN] = {b0.x, b0.y, b0.z, b0.w, b1.x, b1.y, b1.z, b1.w};
#pragma unroll
            for (int i = 0; i < TM; i++)
#pragma unroll
                for (int j = 0; j < TN; j++) acc[i][j] += a[i] * b[j];
        }
        __syncthreads();
    }

    // epilogue (split-half mapping)
    int mrow[TM], ncol[TN];
#pragma unroll
    for (int i = 0; i < 4; i++) {
        mrow[i]     = m0 + ty * 4 + i;
        mrow[i + 4] = m0 + BM / 2 + ty * 4 + i;
        ncol[i]     = n0 + tx * 4 + i;
        ncol[i + 4] = n0 + BN / 2 + tx * 4 + i;
    }
#pragma unroll
    for (int i = 0; i < TM; i++) {
        const float bi = bias ? bias[mrow[i]] : 0.f;
#pragma unroll
        for (int j = 0; j < TN; j++) {
            float v = alpha * acc[i][j] + bi;
            if (resid) v += resid[(long)mrow[i] * ldc + ncol[j]];
            C[(long)mrow[i] * ldc + ncol[j]] = v;
        }
    }
}

// ---------------------------------------------------------------------------
// Launch
// ---------------------------------------------------------------------------
extern "C" void kernel_launch(void* const* d_in, const int* in_sizes, int n_in,
                              void* d_out, int out_size) {
    const float* x      = (const float*)d_in[0];
    const float* norm_w = (const float*)d_in[1];
    const float* norm_b = (const float*)d_in[2];
    const float* qkv_w  = (const float*)d_in[3];
    const float* qkv_b  = (const float*)d_in[4];
    const float* proj_w = (const float*)d_in[5];
    const float* proj_b = (const float*)d_in[6];
    float* out = (float*)d_out;

    float *h, *qkv, *attn, *o;
    cudaGetSymbolAddress((void**)&h,    g_h);
    cudaGetSymbolAddress((void**)&qkv,  g_qkv);
    cudaGetSymbolAddress((void**)&attn, g_attn);
    cudaGetSymbolAddress((void**)&o,    g_o);

    const long CS  = (long)C_DIM * S_DIM;      // 512*1024
    const long SS  = (long)S_DIM * S_DIM;      // 1024*1024
    const long HDS = (long)HD * S_DIM;         // 64*1024

    // 1. GroupNorm
    groupnorm_kernel<<<B_DIM * NG, 256>>>(x, norm_w, norm_b, h);

    // 2. QKV: Y[3C,S] = W[3C,C] @ h[C,S] + b, per batch
    {
        dim3 grid(S_DIM / 128, (3 * C_DIM) / 128, B_DIM);
        sgemm_kernel<128, 128, 8, false, true><<<grid, 256>>>(
            qkv_w, h, qkv, qkv_b, nullptr,
            3 * C_DIM, S_DIM, C_DIM,
            C_DIM, S_DIM, S_DIM,
            1,
            0, 0,            // A: shared weights
            CS, 0,           // B: h per batch
            3 * CS, 0,       // C: qkv per batch
            0, 1.0f);
    }

    // 3. Scores: S[s,t] = 0.125 * sum_d Q[d,s] K[d,t], per (b,head)
    {
        dim3 grid(S_DIM / 128, S_DIM / 128, B_DIM * NH);
        sgemm_kernel<128, 128, 8, true, true><<<grid, 256>>>(
            qkv /*Q base*/, qkv + CS /*K base*/, attn, nullptr, nullptr,
            S_DIM, S_DIM, HD,
            S_DIM, S_DIM, S_DIM,
            NH,
            3 * CS, HDS,     // A: Q per (b,h)
            3 * CS, HDS,     // B: K per (b,h)
            (long)NH * SS, SS,
            0, 0.125f);
    }

    // 4. Softmax over t (rows of attn)
    softmax_kernel<<<B_DIM * NH * S_DIM, 256>>>(attn);

    // 5. PV: O[d,s] = sum_t V[d,t] P[s,t]  (A=[M,K], B=[N,K])
    {
        dim3 grid(S_DIM / 128, 1, B_DIM * NH);
        sgemm_kernel<64, 128, 8, false, false><<<grid, 128>>>(
            qkv + 2 * CS /*V base*/, attn, o, nullptr, nullptr,
            HD, S_DIM, S_DIM,
            S_DIM, S_DIM, S_DIM,
            NH,
            3 * CS, HDS,          // A: V per (b,h)
            (long)NH * SS, SS,    // B: attn per (b,h)
            CS, HDS,              // C: o per (b,h)
            0, 1.0f);
    }

    // 6. Proj + bias + residual
    {
        dim3 grid(S_DIM / 128, C_DIM / 128, B_DIM);
        sgemm_kernel<128, 128, 8, false, true><<<grid, 256>>>(
            proj_w, o, out, proj_b, x,
            C_DIM, S_DIM, C_DIM,
            C_DIM, S_DIM, S_DIM,
            1,
            0, 0,
            CS, 0,
            CS, 0,
            CS, 1.0f);
    }
}

// round 3
// speedup vs baseline: 5.9819x; 5.9819x over previous
#include <cuda_runtime.h>
#include <cuda_fp16.h>
#include <cstdint>
#include <math.h>

#define B_DIM 16
#define C_DIM 512
#define S_DIM 1024
#define NG    32
#define NH    8
#define HD    64

// ---------------- scratch (allocation-free __device__ globals) ----------------
__device__ __half g_h   [(size_t)B_DIM * S_DIM * C_DIM];          // [b,s,c]    16 MB
__device__ __half g_qkv [(size_t)B_DIM * S_DIM * 3 * C_DIM];      // [b,s,o]    48 MB
__device__ float  g_attn[(size_t)B_DIM * NH * S_DIM * S_DIM];     // [bh,s,t]  512 MB
__device__ __half g_p   [(size_t)B_DIM * NH * S_DIM * S_DIM];     // [bh,s,t]  256 MB
__device__ __half g_vT  [(size_t)B_DIM * NH * HD * S_DIM];        // [bh,d,t]   16 MB
__device__ __half g_o   [(size_t)B_DIM * S_DIM * C_DIM];          // [b,s,c]    16 MB
__device__ __half g_wq  [3 * C_DIM * C_DIM];                      // qkv_w fp16
__device__ __half g_wp  [C_DIM * C_DIM];                          // proj_w fp16
__device__ float  g_mean[B_DIM * NG];
__device__ float  g_inv [B_DIM * NG];

// ---------------- helpers ----------------
__device__ __forceinline__ uint32_t smem_u32(const void* p) {
    return (uint32_t)__cvta_generic_to_shared(p);
}

__device__ __forceinline__ void cp16(void* smem_dst, const void* gmem_src) {
    asm volatile("cp.async.ca.shared.global [%0], [%1], 16;"
                 :: "r"(smem_u32(smem_dst)), "l"(gmem_src));
}
__device__ __forceinline__ void cp_commit() {
    asm volatile("cp.async.commit_group;" ::: "memory");
}
template <int N>
__device__ __forceinline__ void cp_wait() {
    asm volatile("cp.async.wait_group %0;" :: "n"(N) : "memory");
}

__device__ __forceinline__ void ldm_x4(uint32_t& r0, uint32_t& r1, uint32_t& r2,
                                       uint32_t& r3, const void* p) {
    asm volatile("ldmatrix.sync.aligned.m8n8.x4.shared.b16 {%0,%1,%2,%3}, [%4];"
                 : "=r"(r0), "=r"(r1), "=r"(r2), "=r"(r3) : "r"(smem_u32(p)));
}
__device__ __forceinline__ void ldm_x2(uint32_t& r0, uint32_t& r1, const void* p) {
    asm volatile("ldmatrix.sync.aligned.m8n8.x2.shared.b16 {%0,%1}, [%2];"
                 : "=r"(r0), "=r"(r1) : "r"(smem_u32(p)));
}
__device__ __forceinline__ void mma16816(float* c, const uint32_t* a, const uint32_t* b) {
    asm volatile(
        "mma.sync.aligned.m16n8k16.row.col.f32.f16.f16.f32 "
        "{%0,%1,%2,%3}, {%4,%5,%6,%7}, {%8,%9}, {%0,%1,%2,%3};"
        : "+f"(c[0]), "+f"(c[1]), "+f"(c[2]), "+f"(c[3])
        : "r"(a[0]), "r"(a[1]), "r"(a[2]), "r"(a[3]), "r"(b[0]), "r"(b[1]));
}

// ---------------------------------------------------------------------------
// fp32 -> fp16 convert (weights)
// ---------------------------------------------------------------------------
__global__ void convert_kernel(const float* __restrict__ src,
                               __half* __restrict__ dst, int n) {
    int i = blockIdx.x * blockDim.x + threadIdx.x;
    if (i < n) dst[i] = __float2half(src[i]);
}

// ---------------------------------------------------------------------------
// GroupNorm pass 1: per (b,g) mean / inv-std
// ---------------------------------------------------------------------------
__global__ void gn_stats_kernel(const float* __restrict__ x,
                                float* __restrict__ meanArr,
                                float* __restrict__ invArr) {
    const int bg = blockIdx.x;
    const int NEL = (C_DIM / NG) * S_DIM;
    const float* xp = x + (size_t)bg * NEL;
    float sum = 0.f, sq = 0.f;
    for (int i = threadIdx.x; i < NEL; i += 256) {
        float v = xp[i];
        sum += v; sq += v * v;
    }
    __shared__ float ssum[256], ssq[256];
    ssum[threadIdx.x] = sum; ssq[threadIdx.x] = sq;
    __syncthreads();
    for (int s = 128; s > 0; s >>= 1) {
        if (threadIdx.x < s) {
            ssum[threadIdx.x] += ssum[threadIdx.x + s];
            ssq[threadIdx.x]  += ssq[threadIdx.x + s];
        }
        __syncthreads();
    }
    if (threadIdx.x == 0) {
        float mean = ssum[0] * (1.f / NEL);
        float var  = ssq[0] * (1.f / NEL) - mean * mean;
        meanArr[bg] = mean;
        invArr[bg]  = rsqrtf(var + 1e-5f);
    }
}

// ---------------------------------------------------------------------------
// GroupNorm pass 2 + transpose -> h[b,s,c] fp16
// ---------------------------------------------------------------------------
__global__ void gn_transpose_kernel(const float* __restrict__ x,
                                    const float* __restrict__ gamma,
                                    const float* __restrict__ beta,
                                    const float* __restrict__ meanArr,
                                    const float* __restrict__ invArr,
                                    __half* __restrict__ h) {
    __shared__ float t[32][33];
    const int b = blockIdx.z, c0 = blockIdx.y * 32, s0 = blockIdx.x * 32;
    const int tx = threadIdx.x, ty = threadIdx.y;
#pragma unroll
    for (int i = 0; i < 4; i++) {
        int c = c0 + ty + i * 8;
        float v = x[((size_t)b * C_DIM + c) * S_DIM + s0 + tx];
        int g = c >> 4;
        float mean = meanArr[b * NG + g], inv = invArr[b * NG + g];
        t[ty + i * 8][tx] = (v - mean) * inv * gamma[c] + beta[c];
    }
    __syncthreads();
#pragma unroll
    for (int i = 0; i < 4; i++) {
        int s = s0 + ty + i * 8;
        h[((size_t)b * S_DIM + s) * C_DIM + c0 + tx] = __float2half(t[tx][ty + i * 8]);
    }
}

// ---------------------------------------------------------------------------
// V transpose: vT[bh,d,t] = qkv[b,t,1024 + h*64 + d]   (fp16)
// ---------------------------------------------------------------------------
__global__ void v_transpose_kernel(const __half* __restrict__ qkv,
                                   __half* __restrict__ vT) {
    __shared__ __half t[32][33];
    const int bh = blockIdx.z, b = bh >> 3, hh = bh & 7;
    const int d0 = blockIdx.y * 32, t0 = blockIdx.x * 32;
    const int tx = threadIdx.x, ty = threadIdx.y;
    const __half* src = qkv + (size_t)b * S_DIM * 3 * C_DIM + 2 * C_DIM + hh * HD;
#pragma unroll
    for (int i = 0; i < 4; i++)
        t[ty + i * 8][tx] = src[(size_t)(t0 + ty + i * 8) * (3 * C_DIM) + d0 + tx];
    __syncthreads();
    __half* dst = vT + (size_t)bh * HD * S_DIM;
#pragma unroll
    for (int i = 0; i < 4; i++)
        dst[(size_t)(d0 + ty + i * 8) * S_DIM + t0 + tx] = t[tx][ty + i * 8];
}

// ---------------------------------------------------------------------------
// Softmax: read fp32 scores row (1024), write fp16 probabilities
// ---------------------------------------------------------------------------
__global__ void softmax_kernel(const float* __restrict__ attn,
                               __half* __restrict__ p) {
    const float4* row = reinterpret_cast<const float4*>(attn + (size_t)blockIdx.x * S_DIM);
    __half2* prow = reinterpret_cast<__half2*>(p + (size_t)blockIdx.x * S_DIM);
    const int tid = threadIdx.x;
    float4 v = row[tid];

    float m = fmaxf(fmaxf(v.x, v.y), fmaxf(v.z, v.w));
#pragma unroll
    for (int o = 16; o; o >>= 1) m = fmaxf(m, __shfl_xor_sync(0xffffffffu, m, o));
    __shared__ float red[8];
    if ((tid & 31) == 0) red[tid >> 5] = m;
    __syncthreads();
    float rmax = fmaxf(fmaxf(fmaxf(red[0], red[1]), fmaxf(red[2], red[3])),
                       fmaxf(fmaxf(red[4], red[5]), fmaxf(red[6], red[7])));
    v.x = __expf(v.x - rmax); v.y = __expf(v.y - rmax);
    v.z = __expf(v.z - rmax); v.w = __expf(v.w - rmax);
    float s = (v.x + v.y) + (v.z + v.w);
#pragma unroll
    for (int o = 16; o; o >>= 1) s += __shfl_xor_sync(0xffffffffu, s, o);
    __syncthreads();
    if ((tid & 31) == 0) red[tid >> 5] = s;
    __syncthreads();
    float tot = ((red[0] + red[1]) + (red[2] + red[3])) +
                ((red[4] + red[5]) + (red[6] + red[7]));
    float rinv = 1.f / tot;
    prow[tid * 2]     = __floats2half2_rn(v.x * rinv, v.y * rinv);
    prow[tid * 2 + 1] = __floats2half2_rn(v.z * rinv, v.w * rinv);
}

// ---------------------------------------------------------------------------
// HGEMM via mma.sync m16n8k16 (fp16 in, fp32 acc).
//   D[m,n] = alpha * sum_k A[m,k]*B[n,k] (+bias) (+resid), stored C[m*ldc+n]
//   A: [M,K] K-major (lda), B: [N,K] K-major (ldb), K % 32 == 0.
//   BIAS_MODE: 0 none, 1 per-m, 2 per-n.  OutT: float or __half.
//   256 threads, 8 warps (2m x 4n), warp tile 64 x (BN/4), 2-stage cp.async.
// ---------------------------------------------------------------------------
template <int BN, int BIAS_MODE, bool RESID, typename OutT>
__global__ __launch_bounds__(256)
void hgemm_kernel(const __half* __restrict__ A, const __half* __restrict__ B,
                  OutT* __restrict__ C, const float* __restrict__ bias,
                  const float* __restrict__ resid,
                  int K, int lda, int ldb, int ldc, int nInner,
                  long sAo, long sAi, long sBo, long sBi,
                  long sCo, long sCi, float alpha) {
    constexpr int BM = 128, BK = 32;
    constexpr int WN = BN / 4;            // warp n extent
    constexpr int NT = WN / 8;            // n8 tiles per warp
    constexpr int SK = BK + 8;            // padded stride (80B) -> conflict-free ldmatrix

    __shared__ __half As[2][BM][SK];
    __shared__ __half Bs[2][BN][SK];

    const int tid = threadIdx.x;
    const int lane = tid & 31, wid = tid >> 5;
    const int wm = wid & 1, wn = wid >> 1;

    const int z = blockIdx.z;
    const int zo = z / nInner, zi = z - zo * nInner;
    A += zo * sAo + zi * sAi;
    B += zo * sBo + zi * sBi;
    const size_t cbase = (size_t)(zo * sCo + zi * sCi);
    const int m0 = blockIdx.y * BM;
    const int n0 = blockIdx.x * BN;

    const int lrow = tid >> 2;            // 0..63
    const int lcol = (tid & 3) * 8;       // 16B chunk within 32-half row

    float acc[4][NT][4];
#pragma unroll
    for (int i = 0; i < 4; i++)
#pragma unroll
        for (int j = 0; j < NT; j++)
#pragma unroll
            for (int q = 0; q < 4; q++) acc[i][j][q] = 0.f;

    const int nit = K >> 5;

    // ---- stage loader ----
    auto load_stage = [&](int st, int it) {
        const int k0 = it << 5;
#pragma unroll
        for (int p = 0; p < BM / 64; p++) {
            int r = lrow + p * 64;
            cp16(&As[st][r][lcol], A + (size_t)(m0 + r) * lda + k0 + lcol);
        }
#pragma unroll
        for (int p = 0; p < BN / 64; p++) {
            int r = lrow + p * 64;
            cp16(&Bs[st][r][lcol], B + (size_t)(n0 + r) * ldb + k0 + lcol);
        }
        cp_commit();
    };

    load_stage(0, 0);

    for (int it = 0; it < nit; it++) {
        if (it + 1 < nit) {
            load_stage((it + 1) & 1, it + 1);
            cp_wait<1>();
        } else {
            cp_wait<0>();
        }
        __syncthreads();

        const int st = it & 1;
#pragma unroll
        for (int ks = 0; ks < 2; ks++) {
            const int kb = ks * 16;
            uint32_t a[4][4], b[NT][2];
#pragma unroll
            for (int tm = 0; tm < 4; tm++)
                ldm_x4(a[tm][0], a[tm][1], a[tm][2], a[tm][3],
                       &As[st][wm * 64 + tm * 16 + (lane & 15)][kb + ((lane >> 4) << 3)]);
#pragma unroll
            for (int tn = 0; tn < NT; tn++)
                ldm_x2(b[tn][0], b[tn][1],
                       &Bs[st][wn * WN + tn * 8 + (lane & 7)][kb + ((lane >> 3) & 1) * 8]);
#pragma unroll
            for (int tm = 0; tm < 4; tm++)
#pragma unroll
                for (int tn = 0; tn < NT; tn++)
                    mma16816(acc[tm][tn], a[tm], b[tn]);
        }
        __syncthreads();
    }

    // ---- epilogue: C[m*ldc+n] ----
#pragma unroll
    for (int tm = 0; tm < 4; tm++) {
        const int row = m0 + wm * 64 + tm * 16 + (lane >> 2);
#pragma unroll
        for (int tn = 0; tn < NT; tn++) {
            const int col = n0 + wn * WN + tn * 8 + (lane & 3) * 2;
            float v0 = acc[tm][tn][0] * alpha, v1 = acc[tm][tn][1] * alpha;
            float v2 = acc[tm][tn][2] * alpha, v3 = acc[tm][tn][3] * alpha;
            if (BIAS_MODE == 1) {
                v0 += bias[row]; v1 += bias[row];
                v2 += bias[row + 8]; v3 += bias[row + 8];
            }
            if (BIAS_MODE == 2) {
                v0 += bias[col]; v2 += bias[col];
                v1 += bias[col + 1]; v3 += bias[col + 1];
            }
            const size_t a0 = cbase + (size_t)row * ldc + col;
            const size_t a1 = cbase + (size_t)(row + 8) * ldc + col;
            if (sizeof(OutT) == 4) {
                float2 r0 = make_float2(v0, v1), r1 = make_float2(v2, v3);
                if (RESID) {
                    float2 x0 = *(const float2*)(resid + a0);
                    float2 x1 = *(const float2*)(resid + a1);
                    r0.x += x0.x; r0.y += x0.y; r1.x += x1.x; r1.y += x1.y;
                }
                *(float2*)((float*)C + a0) = r0;
                *(float2*)((float*)C + a1) = r1;
            } else {
                *(__half2*)((__half*)C + a0) = __floats2half2_rn(v0, v1);
                *(__half2*)((__half*)C + a1) = __floats2half2_rn(v2, v3);
            }
        }
    }
}

// ---------------------------------------------------------------------------
// Launch
// ---------------------------------------------------------------------------
extern "C" void kernel_launch(void* const* d_in, const int* in_sizes, int n_in,
                              void* d_out, int out_size) {
    const float* x      = (const float*)d_in[0];
    const float* norm_w = (const float*)d_in[1];
    const float* norm_b = (const float*)d_in[2];
    const float* qkv_w  = (const float*)d_in[3];
    const float* qkv_b  = (const float*)d_in[4];
    const float* proj_w = (const float*)d_in[5];
    const float* proj_b = (const float*)d_in[6];
    float* out = (float*)d_out;

    __half *h, *qkv, *p, *vT, *obuf, *wq, *wp;
    float *attn, *meanA, *invA;
    cudaGetSymbolAddress((void**)&h,     g_h);
    cudaGetSymbolAddress((void**)&qkv,   g_qkv);
    cudaGetSymbolAddress((void**)&attn,  g_attn);
    cudaGetSymbolAddress((void**)&p,     g_p);
    cudaGetSymbolAddress((void**)&vT,    g_vT);
    cudaGetSymbolAddress((void**)&obuf,  g_o);
    cudaGetSymbolAddress((void**)&wq,    g_wq);
    cudaGetSymbolAddress((void**)&wp,    g_wp);
    cudaGetSymbolAddress((void**)&meanA, g_mean);
    cudaGetSymbolAddress((void**)&invA,  g_inv);

    const long SS  = (long)S_DIM * S_DIM;       // 1M
    const long SC  = (long)S_DIM * C_DIM;       // 512K
    const long S3C = (long)S_DIM * 3 * C_DIM;   // 1.5M
    const long HDS = (long)HD * S_DIM;          // 64K

    // 0. fp16 weight copies
    convert_kernel<<<(3 * C_DIM * C_DIM + 255) / 256, 256>>>(qkv_w, wq, 3 * C_DIM * C_DIM);
    convert_kernel<<<(C_DIM * C_DIM + 255) / 256, 256>>>(proj_w, wp, C_DIM * C_DIM);

    // 1. GroupNorm -> h[b,s,c] fp16
    gn_stats_kernel<<<B_DIM * NG, 256>>>(x, meanA, invA);
    gn_transpose_kernel<<<dim3(32, 16, 16), dim3(32, 8)>>>(x, norm_w, norm_b,
                                                           meanA, invA, h);

    // 2. QKV: M=s(1024), N=o(1536), K=512.  A=h[b][s,c], B=wq[o,c].
    //    C[m*1536+n] = qkv[b,s,o], bias per n, out fp16.
    hgemm_kernel<128, 2, false, __half><<<dim3(12, 8, 16), 256>>>(
        h, wq, qkv, qkv_b, nullptr,
        512, 512, 512, 1536,
        1, SC, 0, 0, 0, S3C, 0, 1.0f);

    // 3. V transpose -> vT[bh,d,t]
    v_transpose_kernel<<<dim3(32, 2, 128), dim3(32, 8)>>>(qkv, vT);

    // 4. Scores: M=s, N=t, K=64. A=Q rows, B=K rows (both in qkv, ld=1536).
    //    C[m*1024+n] = attn[bh,s,t] fp32, alpha=0.125.
    hgemm_kernel<128, 0, false, float><<<dim3(8, 8, 128), 256>>>(
        qkv, qkv + 512, attn, nullptr, nullptr,
        64, 1536, 1536, 1024,
        8, S3C, 64, S3C, 64, 8 * SS, SS, 0.125f);

    // 5. Softmax -> p fp16
    softmax_kernel<<<B_DIM * NH * S_DIM, 256>>>(attn, p);

    // 6. PV: M=s(1024), N=d(64), K=1024. A=p[bh][s,t], B=vT[bh][d,t].
    //    C[m*512 + h*64 + n] = obuf fp16.
    hgemm_kernel<64, 0, false, __half><<<dim3(1, 8, 128), 256>>>(
        p, vT, obuf, nullptr, nullptr,
        1024, 1024, 1024, 512,
        8, 8 * SS, SS, 8 * HDS, HDS, SC, 64, 1.0f);

    // 7. Proj: M=co(512), N=s(1024), K=512. A=wp[co,c], B=obuf[b][s,c].
    //    C[m*1024+n] = out[b,co,s] fp32, bias per m, resid = x.
    hgemm_kernel<128, 1, true, float><<<dim3(8, 4, 16), 256>>>(
        wp, obuf, out, proj_b, x,
        512, 512, 512, 1024,
        1, 0, 0, SC, 0, SC, 0, 1.0f);
}

// round 5
// speedup vs baseline: 10.7592x; 1.7986x over previous
#include <cuda_runtime.h>
#include <cuda_fp16.h>
#include <cstdint>
#include <math.h>

#define B_DIM 16
#define C_DIM 512
#define S_DIM 1024
#define NG    32
#define NH    8
#define HD    64

// ---------------- scratch (allocation-free __device__ globals) ----------------
__device__ __half g_h   [(size_t)B_DIM * S_DIM * C_DIM];          // [b,s,c]  16 MB
__device__ __half g_qkv [(size_t)B_DIM * S_DIM * 3 * C_DIM];      // [b,s,o]  48 MB
__device__ __half g_o   [(size_t)B_DIM * S_DIM * C_DIM];          // [b,s,c]  16 MB
__device__ __half g_wq  [3 * C_DIM * C_DIM];
__device__ __half g_wp  [C_DIM * C_DIM];
__device__ float  g_mean[B_DIM * NG];
__device__ float  g_inv [B_DIM * NG];

// ---------------- helpers ----------------
__device__ __forceinline__ uint32_t smem_u32(const void* p) {
    return (uint32_t)__cvta_generic_to_shared(p);
}
__device__ __forceinline__ void cp16(void* smem_dst, const void* gmem_src) {
    asm volatile("cp.async.ca.shared.global [%0], [%1], 16;"
                 :: "r"(smem_u32(smem_dst)), "l"(gmem_src));
}
__device__ __forceinline__ void cp_commit() {
    asm volatile("cp.async.commit_group;" ::: "memory");
}
template <int N>
__device__ __forceinline__ void cp_wait() {
    asm volatile("cp.async.wait_group %0;" :: "n"(N) : "memory");
}
__device__ __forceinline__ void ldm_x4(uint32_t& r0, uint32_t& r1, uint32_t& r2,
                                       uint32_t& r3, const void* p) {
    asm volatile("ldmatrix.sync.aligned.m8n8.x4.shared.b16 {%0,%1,%2,%3}, [%4];"
                 : "=r"(r0), "=r"(r1), "=r"(r2), "=r"(r3) : "r"(smem_u32(p)));
}
__device__ __forceinline__ void ldm_x4t(uint32_t& r0, uint32_t& r1, uint32_t& r2,
                                        uint32_t& r3, const void* p) {
    asm volatile("ldmatrix.sync.aligned.m8n8.x4.trans.shared.b16 {%0,%1,%2,%3}, [%4];"
                 : "=r"(r0), "=r"(r1), "=r"(r2), "=r"(r3) : "r"(smem_u32(p)));
}
__device__ __forceinline__ void ldm_x2(uint32_t& r0, uint32_t& r1, const void* p) {
    asm volatile("ldmatrix.sync.aligned.m8n8.x2.shared.b16 {%0,%1}, [%2];"
                 : "=r"(r0), "=r"(r1) : "r"(smem_u32(p)));
}
__device__ __forceinline__ void mma16816(float* c, const uint32_t* a, const uint32_t* b) {
    asm volatile(
        "mma.sync.aligned.m16n8k16.row.col.f32.f16.f16.f32 "
        "{%0,%1,%2,%3}, {%4,%5,%6,%7}, {%8,%9}, {%0,%1,%2,%3};"
        : "+f"(c[0]), "+f"(c[1]), "+f"(c[2]), "+f"(c[3])
        : "r"(a[0]), "r"(a[1]), "r"(a[2]), "r"(a[3]), "r"(b[0]), "r"(b[1]));
}
__device__ __forceinline__ float ex2(float x) {
    float y;
    asm("ex2.approx.ftz.f32 %0, %1;" : "=f"(y) : "f"(x));
    return y;
}
__device__ __forceinline__ uint32_t h2_as_u32(__half2 h) {
    return *reinterpret_cast<uint32_t*>(&h);
}

// ---------------------------------------------------------------------------
// fp32 -> fp16 weight convert
// ---------------------------------------------------------------------------
__global__ void convert_kernel(const float* __restrict__ src,
                               __half* __restrict__ dst, int n) {
    int i = blockIdx.x * blockDim.x + threadIdx.x;
    if (i < n) dst[i] = __float2half(src[i]);
}

// ---------------------------------------------------------------------------
// GroupNorm pass 1: per (b,g) mean / inv-std
// ---------------------------------------------------------------------------
__global__ void gn_stats_kernel(const float* __restrict__ x,
                                float* __restrict__ meanArr,
                                float* __restrict__ invArr) {
    const int bg = blockIdx.x;
    const int NEL = (C_DIM / NG) * S_DIM;
    const float* xp = x + (size_t)bg * NEL;
    float sum = 0.f, sq = 0.f;
    for (int i = threadIdx.x; i < NEL; i += 256) {
        float v = xp[i];
        sum += v; sq += v * v;
    }
    __shared__ float ssum[256], ssq[256];
    ssum[threadIdx.x] = sum; ssq[threadIdx.x] = sq;
    __syncthreads();
    for (int s = 128; s > 0; s >>= 1) {
        if (threadIdx.x < s) {
            ssum[threadIdx.x] += ssum[threadIdx.x + s];
            ssq[threadIdx.x]  += ssq[threadIdx.x + s];
        }
        __syncthreads();
    }
    if (threadIdx.x == 0) {
        float mean = ssum[0] * (1.f / NEL);
        float var  = ssq[0] * (1.f / NEL) - mean * mean;
        meanArr[bg] = mean;
        invArr[bg]  = rsqrtf(var + 1e-5f);
    }
}

// ---------------------------------------------------------------------------
// GroupNorm pass 2 + transpose -> h[b,s,c] fp16
// ---------------------------------------------------------------------------
__global__ void gn_transpose_kernel(const float* __restrict__ x,
                                    const float* __restrict__ gamma,
                                    const float* __restrict__ beta,
                                    const float* __restrict__ meanArr,
                                    const float* __restrict__ invArr,
                                    __half* __restrict__ h) {
    __shared__ float t[32][33];
    const int b = blockIdx.z, c0 = blockIdx.y * 32, s0 = blockIdx.x * 32;
    const int tx = threadIdx.x, ty = threadIdx.y;
#pragma unroll
    for (int i = 0; i < 4; i++) {
        int c = c0 + ty + i * 8;
        float v = x[((size_t)b * C_DIM + c) * S_DIM + s0 + tx];
        int g = c >> 4;
        float mean = meanArr[b * NG + g], inv = invArr[b * NG + g];
        t[ty + i * 8][tx] = (v - mean) * inv * gamma[c] + beta[c];
    }
    __syncthreads();
#pragma unroll
    for (int i = 0; i < 4; i++) {
        int s = s0 + ty + i * 8;
        h[((size_t)b * S_DIM + s) * C_DIM + c0 + tx] = __float2half(t[tx][ty + i * 8]);
    }
}

// ---------------------------------------------------------------------------
// Fused flash attention (fp16 mma, fp32 online softmax).
// Grid: (S/128, B*NH). 256 thr = 8 warps; warp w owns rows s0+w*16..+15.
// qkv layout [b, s, 3C]: q @ h*64, k @ 512+h*64, v @ 1024+h*64, row stride 1536.
// Output o[b, s, h*64+d] fp16.
// ---------------------------------------------------------------------------
#define SMK 72          // padded smem row stride (halves) -> conflict-free ldmatrix
#define FLASH_SMEM (5 * 128 * SMK * 2)

__global__ __launch_bounds__(256)
void flash_kernel(const __half* __restrict__ qkv, __half* __restrict__ o) {
    extern __shared__ __half sm[];
    __half (*Qs)[SMK] = reinterpret_cast<__half(*)[SMK]>(sm);
    __half (*Ks)[SMK] = reinterpret_cast<__half(*)[SMK]>(sm + 128 * SMK);      // 2 stages
    __half (*Vs)[SMK] = reinterpret_cast<__half(*)[SMK]>(sm + 3 * 128 * SMK);  // 2 stages

    const int tid = threadIdx.x, lane = tid & 31, w = tid >> 5;
    const int bh = blockIdx.y, b = bh >> 3, hh = bh & 7;
    const int s0 = blockIdx.x * 128;

    const __half* qbase = qkv + (size_t)b * (S_DIM * 3 * C_DIM) + hh * 64;
    const __half* kbase = qbase + 512;
    const __half* vbase = qbase + 1024;

    const int ldrow = tid >> 1;          // 0..127
    const int ldcol = (tid & 1) * 32;    // 0 or 32 halves

    // stage Q
#pragma unroll
    for (int c = 0; c < 4; c++)
        cp16(&Qs[ldrow][ldcol + c * 8],
             qbase + (size_t)(s0 + ldrow) * 1536 + ldcol + c * 8);
    cp_commit();
    // stage K/V tile 0
    {
        const __half* kp = kbase + (size_t)ldrow * 1536 + ldcol;
        const __half* vp = vbase + (size_t)ldrow * 1536 + ldcol;
#pragma unroll
        for (int c = 0; c < 4; c++) {
            cp16(&Ks[ldrow][ldcol + c * 8], kp + c * 8);
            cp16(&Vs[ldrow][ldcol + c * 8], vp + c * 8);
        }
    }
    cp_commit();
    cp_wait<1>();           // Q complete
    __syncthreads();

    // Q fragments (held whole loop)
    uint32_t qf[4][4];
#pragma unroll
    for (int kj = 0; kj < 4; kj++)
        ldm_x4(qf[kj][0], qf[kj][1], qf[kj][2], qf[kj][3],
               &Qs[w * 16 + (lane & 15)][kj * 16 + ((lane >> 4) << 3)]);

    const float C2 = 0.125f * 1.44269504f;   // scale * log2(e)
    float m0 = -1e30f, m1 = -1e30f, l0 = 0.f, l1 = 0.f;
    float ao[8][4];
#pragma unroll
    for (int i = 0; i < 8; i++)
#pragma unroll
        for (int j = 0; j < 4; j++) ao[i][j] = 0.f;

    for (int it = 0; it < 8; it++) {
        if (it < 7) {
            const int stn = (it + 1) & 1;
            const __half* kp = kbase + (size_t)((it + 1) * 128 + ldrow) * 1536 + ldcol;
            const __half* vp = vbase + (size_t)((it + 1) * 128 + ldrow) * 1536 + ldcol;
#pragma unroll
            for (int c = 0; c < 4; c++) {
                cp16(&Ks[stn * 128 + ldrow][ldcol + c * 8], kp + c * 8);
                cp16(&Vs[stn * 128 + ldrow][ldcol + c * 8], vp + c * 8);
            }
            cp_commit();
            cp_wait<1>();
        } else {
            cp_wait<0>();
        }
        __syncthreads();
        const int st = it & 1;

        // ---- S = Q K^T  (16 n8-tiles x k=64) ----
        float as[16][4];
#pragma unroll
        for (int i = 0; i < 16; i++)
#pragma unroll
            for (int j = 0; j < 4; j++) as[i][j] = 0.f;

#pragma unroll
        for (int kj = 0; kj < 4; kj++) {
            uint32_t bf[8][4];
#pragma unroll
            for (int j = 0; j < 8; j++)
                ldm_x4(bf[j][0], bf[j][1], bf[j][2], bf[j][3],
                       &Ks[st * 128 + j * 16 + (lane & 15)]
                          [kj * 16 + ((lane >> 4) << 3)]);
#pragma unroll
            for (int j = 0; j < 8; j++) {
                uint32_t bA[2] = {bf[j][0], bf[j][2]};
                uint32_t bB[2] = {bf[j][1], bf[j][3]};
                mma16816(as[2 * j],     qf[kj], bA);
                mma16816(as[2 * j + 1], qf[kj], bB);
            }
        }

        // ---- online softmax ----
        float mx0 = -1e30f, mx1 = -1e30f;
#pragma unroll
        for (int nt = 0; nt < 16; nt++) {
            mx0 = fmaxf(mx0, fmaxf(as[nt][0], as[nt][1]));
            mx1 = fmaxf(mx1, fmaxf(as[nt][2], as[nt][3]));
        }
        mx0 = fmaxf(mx0, __shfl_xor_sync(0xffffffffu, mx0, 1));
        mx0 = fmaxf(mx0, __shfl_xor_sync(0xffffffffu, mx0, 2));
        mx1 = fmaxf(mx1, __shfl_xor_sync(0xffffffffu, mx1, 1));
        mx1 = fmaxf(mx1, __shfl_xor_sync(0xffffffffu, mx1, 2));
        const float mn0 = fmaxf(m0, mx0), mn1 = fmaxf(m1, mx1);
        const float cr0 = ex2((m0 - mn0) * C2), cr1 = ex2((m1 - mn1) * C2);
        m0 = mn0; m1 = mn1;
        l0 *= cr0; l1 *= cr1;
#pragma unroll
        for (int tn = 0; tn < 8; tn++) {
            ao[tn][0] *= cr0; ao[tn][1] *= cr0;
            ao[tn][2] *= cr1; ao[tn][3] *= cr1;
        }

        uint32_t ph[8][4];
        float sum0 = 0.f, sum1 = 0.f;
#pragma unroll
        for (int nt = 0; nt < 16; nt++) {
            float p0 = ex2((as[nt][0] - mn0) * C2);
            float p1 = ex2((as[nt][1] - mn0) * C2);
            float p2 = ex2((as[nt][2] - mn1) * C2);
            float p3 = ex2((as[nt][3] - mn1) * C2);
            sum0 += p0 + p1; sum1 += p2 + p3;
            const int kj = nt >> 1, hi = (nt & 1) * 2;
            ph[kj][hi]     = h2_as_u32(__floats2half2_rn(p0, p1));
            ph[kj][hi + 1] = h2_as_u32(__floats2half2_rn(p2, p3));
        }
        sum0 += __shfl_xor_sync(0xffffffffu, sum0, 1);
        sum0 += __shfl_xor_sync(0xffffffffu, sum0, 2);
        sum1 += __shfl_xor_sync(0xffffffffu, sum1, 1);
        sum1 += __shfl_xor_sync(0xffffffffu, sum1, 2);
        l0 += sum0; l1 += sum1;

        // ---- O += P V  (k=128 over t, n=64 over d) ----
#pragma unroll
        for (int kj = 0; kj < 8; kj++) {
            uint32_t vf[4][4];
#pragma unroll
            for (int dj = 0; dj < 4; dj++)
                ldm_x4t(vf[dj][0], vf[dj][1], vf[dj][2], vf[dj][3],
                        &Vs[st * 128 + kj * 16 + (lane & 15)]
                           [dj * 16 + ((lane >> 4) << 3)]);
#pragma unroll
            for (int dj = 0; dj < 4; dj++) {
                uint32_t bA[2] = {vf[dj][0], vf[dj][1]};
                uint32_t bB[2] = {vf[dj][2], vf[dj][3]};
                mma16816(ao[2 * dj],     ph[kj], bA);
                mma16816(ao[2 * dj + 1], ph[kj], bB);
            }
        }
        __syncthreads();
    }

    // ---- normalize + store ----
    const float r0 = 1.f / l0, r1 = 1.f / l1;
    const int g = lane >> 2;
    const int srow = s0 + w * 16 + g;
    __half* op = o + ((size_t)b * S_DIM + srow) * C_DIM + hh * 64 + (lane & 3) * 2;
#pragma unroll
    for (int tn = 0; tn < 8; tn++) {
        *(__half2*)(op + tn * 8) =
            __floats2half2_rn(ao[tn][0] * r0, ao[tn][1] * r0);
        *(__half2*)(op + 8 * C_DIM + tn * 8) =
            __floats2half2_rn(ao[tn][2] * r1, ao[tn][3] * r1);
    }
}

// ---------------------------------------------------------------------------
// HGEMM via mma.sync m16n8k16 (fp16 in, fp32 acc).
// ---------------------------------------------------------------------------
template <int BN, int BIAS_MODE, bool RESID, typename OutT>
__global__ __launch_bounds__(256)
void hgemm_kernel(const __half* __restrict__ A, const __half* __restrict__ B,
                  OutT* __restrict__ C, const float* __restrict__ bias,
                  const float* __restrict__ resid,
                  int K, int lda, int ldb, int ldc, int nInner,
                  long sAo, long sAi, long sBo, long sBi,
                  long sCo, long sCi, float alpha) {
    constexpr int BM = 128, BK = 32;
    constexpr int WN = BN / 4;
    constexpr int NT = WN / 8;
    constexpr int SK = BK + 8;

    __shared__ __half As[2][BM][SK];
    __shared__ __half Bs[2][BN][SK];

    const int tid = threadIdx.x;
    const int lane = tid & 31, wid = tid >> 5;
    const int wm = wid & 1, wn = wid >> 1;

    const int z = blockIdx.z;
    const int zo = z / nInner, zi = z - zo * nInner;
    A += zo * sAo + zi * sAi;
    B += zo * sBo + zi * sBi;
    const size_t cbase = (size_t)(zo * sCo + zi * sCi);
    const int m0 = blockIdx.y * BM;
    const int n0 = blockIdx.x * BN;

    const int lrow = tid >> 2;
    const int lcol = (tid & 3) * 8;

    float acc[4][NT][4];
#pragma unroll
    for (int i = 0; i < 4; i++)
#pragma unroll
        for (int j = 0; j < NT; j++)
#pragma unroll
            for (int q = 0; q < 4; q++) acc[i][j][q] = 0.f;

    const int nit = K >> 5;

    auto load_stage = [&](int st, int it) {
        const int k0 = it << 5;
#pragma unroll
        for (int p = 0; p < BM / 64; p++) {
            int r = lrow + p * 64;
            cp16(&As[st][r][lcol], A + (size_t)(m0 + r) * lda + k0 + lcol);
        }
#pragma unroll
        for (int p = 0; p < BN / 64; p++) {
            int r = lrow + p * 64;
            cp16(&Bs[st][r][lcol], B + (size_t)(n0 + r) * ldb + k0 + lcol);
        }
        cp_commit();
    };

    load_stage(0, 0);

    for (int it = 0; it < nit; it++) {
        if (it + 1 < nit) {
            load_stage((it + 1) & 1, it + 1);
            cp_wait<1>();
        } else {
            cp_wait<0>();
        }
        __syncthreads();

        const int st = it & 1;
#pragma unroll
        for (int ks = 0; ks < 2; ks++) {
            const int kb = ks * 16;
            uint32_t a[4][4], bfr[NT][2];
#pragma unroll
            for (int tm = 0; tm < 4; tm++)
                ldm_x4(a[tm][0], a[tm][1], a[tm][2], a[tm][3],
                       &As[st][wm * 64 + tm * 16 + (lane & 15)][kb + ((lane >> 4) << 3)]);
#pragma unroll
            for (int tn = 0; tn < NT; tn++)
                ldm_x2(bfr[tn][0], bfr[tn][1],
                       &Bs[st][wn * WN + tn * 8 + (lane & 7)][kb + ((lane >> 3) & 1) * 8]);
#pragma unroll
            for (int tm = 0; tm < 4; tm++)
#pragma unroll
                for (int tn = 0; tn < NT; tn++)
                    mma16816(acc[tm][tn], a[tm], bfr[tn]);
        }
        __syncthreads();
    }

#pragma unroll
    for (int tm = 0; tm < 4; tm++) {
        const int row = m0 + wm * 64 + tm * 16 + (lane >> 2);
#pragma unroll
        for (int tn = 0; tn < NT; tn++) {
            const int col = n0 + wn * WN + tn * 8 + (lane & 3) * 2;
            float v0 = acc[tm][tn][0] * alpha, v1 = acc[tm][tn][1] * alpha;
            float v2 = acc[tm][tn][2] * alpha, v3 = acc[tm][tn][3] * alpha;
            if (BIAS_MODE == 1) {
                v0 += bias[row]; v1 += bias[row];
                v2 += bias[row + 8]; v3 += bias[row + 8];
            }
            if (BIAS_MODE == 2) {
                v0 += bias[col]; v2 += bias[col];
                v1 += bias[col + 1]; v3 += bias[col + 1];
            }
            const size_t a0 = cbase + (size_t)row * ldc + col;
            const size_t a1 = cbase + (size_t)(row + 8) * ldc + col;
            if (sizeof(OutT) == 4) {
                float2 q0 = make_float2(v0, v1), q1 = make_float2(v2, v3);
                if (RESID) {
                    float2 x0 = *(const float2*)(resid + a0);
                    float2 x1 = *(const float2*)(resid + a1);
                    q0.x += x0.x; q0.y += x0.y; q1.x += x1.x; q1.y += x1.y;
                }
                *(float2*)((float*)C + a0) = q0;
                *(float2*)((float*)C + a1) = q1;
            } else {
                *(__half2*)((__half*)C + a0) = __floats2half2_rn(v0, v1);
                *(__half2*)((__half*)C + a1) = __floats2half2_rn(v2, v3);
            }
        }
    }
}

// ---------------------------------------------------------------------------
// Launch
// ---------------------------------------------------------------------------
extern "C" void kernel_launch(void* const* d_in, const int* in_sizes, int n_in,
                              void* d_out, int out_size) {
    const float* x      = (const float*)d_in[0];
    const float* norm_w = (const float*)d_in[1];
    const float* norm_b = (const float*)d_in[2];
    const float* qkv_w  = (const float*)d_in[3];
    const float* qkv_b  = (const float*)d_in[4];
    const float* proj_w = (const float*)d_in[5];
    const float* proj_b = (const float*)d_in[6];
    float* out = (float*)d_out;

    __half *h, *qkv, *obuf, *wq, *wp;
    float *meanA, *invA;
    cudaGetSymbolAddress((void**)&h,     g_h);
    cudaGetSymbolAddress((void**)&qkv,   g_qkv);
    cudaGetSymbolAddress((void**)&obuf,  g_o);
    cudaGetSymbolAddress((void**)&wq,    g_wq);
    cudaGetSymbolAddress((void**)&wp,    g_wp);
    cudaGetSymbolAddress((void**)&meanA, g_mean);
    cudaGetSymbolAddress((void**)&invA,  g_inv);

    const long SC  = (long)S_DIM * C_DIM;
    const long S3C = (long)S_DIM * 3 * C_DIM;

    // 0. fp16 weight copies
    convert_kernel<<<(3 * C_DIM * C_DIM + 255) / 256, 256>>>(qkv_w, wq, 3 * C_DIM * C_DIM);
    convert_kernel<<<(C_DIM * C_DIM + 255) / 256, 256>>>(proj_w, wp, C_DIM * C_DIM);

    // 1. GroupNorm -> h[b,s,c] fp16
    gn_stats_kernel<<<B_DIM * NG, 256>>>(x, meanA, invA);
    gn_transpose_kernel<<<dim3(32, 16, 16), dim3(32, 8)>>>(x, norm_w, norm_b,
                                                           meanA, invA, h);

    // 2. QKV: M=s, N=o(1536), K=512. C[m*1536+n] = qkv[b,s,o] fp16, bias per n.
    hgemm_kernel<128, 2, false, __half><<<dim3(12, 8, 16), 256>>>(
        h, wq, qkv, qkv_b, nullptr,
        512, 512, 512, 1536,
        1, SC, 0, 0, 0, S3C, 0, 1.0f);

    // 3. Fused flash attention -> obuf[b,s,c] fp16
    cudaFuncSetAttribute(flash_kernel,
                         cudaFuncAttributeMaxDynamicSharedMemorySize, FLASH_SMEM);
    flash_kernel<<<dim3(S_DIM / 128, B_DIM * NH), 256, FLASH_SMEM>>>(qkv, obuf);

    // 4. Proj: M=co(512), N=s, K=512. C[m*1024+n] = out[b,co,s] fp32,
    //    bias per m, resid = x.
    hgemm_kernel<128, 1, true, float><<<dim3(8, 4, 16), 256>>>(
        wp, obuf, out, proj_b, x,
        512, 512, 512, 1024,
        1, 0, 0, SC, 0, SC, 0, 1.0f);
}